// round 14
// baseline (speedup 1.0000x reference)
#include <cuda_runtime.h>
#include <math.h>

#define NUM_GRAPHS 8
#define NUM_PASSES 3
#define BN_MAX 400000
#define M_MAX 2048
#define CAP 64            // slots per node; deg ~ Poisson(20), P(any deg>64) ~ 1e-10

// Allocation-free scratch (__device__ globals; ~210MB total)
__device__ int    g_cnt[BN_MAX];                 // per-node edge count / build cursor
__device__ float2 g_pairT[(size_t)CAP * BN_MAX]; // TRANSPOSED buckets: slot-major
                                                 // g_pairT[j*BN + n] = (src_bits, log1p(w))
                                                 // -> pass reads are warp-coalesced
__device__ float  g_A[BN_MAX];
__device__ float  g_B[BN_MAX];
__device__ float  g_C[BN_MAX];

// ---------------------------------------------------------------------------
// Zero the per-node cursors (everything else is plain-stored, no zeroing).
__global__ void zero_kernel(int BN) {
    int i = blockIdx.x * blockDim.x + threadIdx.x;
    if (i < BN) g_cnt[i] = 0;
}

// ---------------------------------------------------------------------------
// Build: bucket edges by dst into fixed-capacity transposed slots. One-time
// cost amortized over NUM_PASSES passes; eliminates per-pass scatter atomics.
// Folds log1p here so no separate lew array/pass is needed.
__global__ void build_kernel(const int4* __restrict__ src4,
                             const int4* __restrict__ dst4,
                             const float4* __restrict__ ew4,
                             int nquad,
                             const int* __restrict__ src_s,
                             const int* __restrict__ dst_s,
                             const float* __restrict__ ew_s,
                             int ntail, int BN) {
    int i = blockIdx.x * blockDim.x + threadIdx.x;
    if (i < nquad) {
        int4   s = src4[i];
        int4   d = dst4[i];
        float4 w = ew4[i];
        int p0 = atomicAdd(&g_cnt[d.x], 1);
        if (p0 < CAP) g_pairT[(size_t)p0 * BN + d.x] = make_float2(__int_as_float(s.x), log1pf(w.x));
        int p1 = atomicAdd(&g_cnt[d.y], 1);
        if (p1 < CAP) g_pairT[(size_t)p1 * BN + d.y] = make_float2(__int_as_float(s.y), log1pf(w.y));
        int p2 = atomicAdd(&g_cnt[d.z], 1);
        if (p2 < CAP) g_pairT[(size_t)p2 * BN + d.z] = make_float2(__int_as_float(s.z), log1pf(w.z));
        int p3 = atomicAdd(&g_cnt[d.w], 1);
        if (p3 < CAP) g_pairT[(size_t)p3 * BN + d.w] = make_float2(__int_as_float(s.w), log1pf(w.w));
    } else if (i - nquad < ntail) {
        int e = nquad * 4 + (i - nquad);
        int d = dst_s[e];
        int p = atomicAdd(&g_cnt[d], 1);
        if (p < CAP) g_pairT[(size_t)p * BN + d] = make_float2(__int_as_float(src_s[e]), log1pf(ew_s[e]));
    }
}

// ---------------------------------------------------------------------------
// Pass: one thread per node; slot-major walk so each warp-step reads 32
// consecutive float2s (256B = 8 sectors) instead of 32 scattered sectors.
// Random L2 ops per pass: 8M h-gathers only (atomics eliminated).
// Raw (unnormalized) accumulation — per-graph L2 norm cancels through the
// linear scatter and is applied once in final_kernel.
__global__ void pass_kernel(const float* __restrict__ h,
                            float* __restrict__ out,
                            int BN) {
    int n = blockIdx.x * blockDim.x + threadIdx.x;
    if (n >= BN) return;
    int cnt = g_cnt[n];
    if (cnt > CAP) cnt = CAP;
    float acc = 0.0f;
    #pragma unroll 4
    for (int j = 0; j < cnt; j++) {
        float2 q = g_pairT[(size_t)j * BN + n];
        acc += h[__float_as_int(q.x)] * q.y;
    }
    out[n] = acc;
}

// ---------------------------------------------------------------------------
// Final: per graph (one block each): sumsq-reduce g_C over N nodes -> scale,
// gather decision neurons (scaled), nonzero-masked standardization, mean pool,
// linear + relu.
__global__ void final_kernel(const int* __restrict__ dm,
                             const float* __restrict__ fc_w,
                             const float* __restrict__ fc_b,
                             float* __restrict__ out,
                             int N, int M) {
    __shared__ float sv[M_MAX];
    __shared__ float red_f[256];
    __shared__ float red_g[256];
    __shared__ float s_scale, s_mean, s_inv_std, s_cnt;

    int b = blockIdx.x;
    int t = threadIdx.x;
    const float* h = g_C + b * N;

    // Phase 0: per-graph sum of squares (vectorized)
    float ss = 0.0f;
    int n4 = N >> 2;
    const float4* h4 = (const float4*)h;
    for (int i = t; i < n4; i += blockDim.x) {
        float4 v = h4[i];
        ss += v.x * v.x + v.y * v.y + v.z * v.z + v.w * v.w;
    }
    for (int i = n4 * 4 + t; i < N; i += blockDim.x) { float v = h[i]; ss += v * v; }
    red_f[t] = ss;
    __syncthreads();
    for (int off = 128; off > 0; off >>= 1) {
        if (t < off) red_f[t] += red_f[t + off];
        __syncthreads();
    }
    if (t == 0) s_scale = rsqrtf(red_f[0]);
    __syncthreads();
    float scale = s_scale;

    // Gather decision neurons, scaled by the (only surviving) normalization
    for (int m = t; m < M; m += blockDim.x)
        sv[m] = h[dm[m]] * scale;
    __syncthreads();

    // Reduction 1: nonzero count + sum
    float sum = 0.0f, cnt = 0.0f;
    for (int m = t; m < M; m += blockDim.x) {
        float v = sv[m];
        if (v != 0.0f) { sum += v; cnt += 1.0f; }
    }
    red_f[t] = sum; red_g[t] = cnt;
    __syncthreads();
    for (int off = 128; off > 0; off >>= 1) {
        if (t < off) { red_f[t] += red_f[t + off]; red_g[t] += red_g[t + off]; }
        __syncthreads();
    }
    if (t == 0) { s_cnt = red_g[0]; s_mean = red_f[0] / red_g[0]; }
    __syncthreads();
    float mean = s_mean, cntv = s_cnt;

    // Reduction 2: sum (v-mean)^2 over nonzeros
    float ss2 = 0.0f;
    for (int m = t; m < M; m += blockDim.x) {
        float v = sv[m];
        if (v != 0.0f) { float d = v - mean; ss2 += d * d; }
    }
    red_f[t] = ss2;
    __syncthreads();
    for (int off = 128; off > 0; off >>= 1) {
        if (t < off) red_f[t] += red_f[t + off];
        __syncthreads();
    }
    if (t == 0) {
        float var = red_f[0] / fmaxf(cntv - 1.0f, 1.0f);
        s_inv_std = 1.0f / (sqrtf(var) + 1e-5f);
    }
    __syncthreads();
    float inv_std = s_inv_std;

    // Reduction 3: sum of standardized values over nonzeros
    float ps = 0.0f;
    for (int m = t; m < M; m += blockDim.x) {
        float v = sv[m];
        if (v != 0.0f) ps += (v - mean) * inv_std;
    }
    red_f[t] = ps;
    __syncthreads();
    for (int off = 128; off > 0; off >>= 1) {
        if (t < off) red_f[t] += red_f[t + off];
        __syncthreads();
    }
    if (t == 0) {
        float pooled = red_f[0] / (float)M;
        float o = pooled * fc_w[0] + fc_b[0];
        out[b] = fmaxf(o, 0.0f);
    }
}

// ---------------------------------------------------------------------------
extern "C" void kernel_launch(void* const* d_in, const int* in_sizes, int n_in,
                              void* d_out, int out_size) {
    const float* x    = (const float*)d_in[0];
    const float* ew   = (const float*)d_in[1];
    const int*   src  = (const int*)d_in[2];
    const int*   dst  = (const int*)d_in[3];
    const int*   dm   = (const int*)d_in[4];
    const float* fc_w = (const float*)d_in[5];
    const float* fc_b = (const float*)d_in[6];
    float* out = (float*)d_out;

    int BN = in_sizes[0];
    int E  = in_sizes[1];
    int M  = in_sizes[4];
    int N  = BN / NUM_GRAPHS;

    // Device addresses of __device__ symbols (host-side &symbol is invalid!)
    static float *pA = nullptr, *pB = nullptr, *pC = nullptr;
    if (pA == nullptr) {
        void* p;
        cudaGetSymbolAddress(&p, g_A); pA = (float*)p;
        cudaGetSymbolAddress(&p, g_B); pB = (float*)p;
        cudaGetSymbolAddress(&p, g_C); pC = (float*)p;
    }

    int nquad = E / 4;
    int ntail = E - nquad * 4;

    const int T = 256;
    int zero_blocks  = (BN + T - 1) / T;
    int build_blocks = (nquad + ntail + T - 1) / T;
    int pass_blocks  = (BN + T - 1) / T;

    // One-time per launch: bucket edges by dst (amortized over 3 passes)
    zero_kernel<<<zero_blocks, T>>>(BN);
    build_kernel<<<build_blocks, T>>>(
        (const int4*)src, (const int4*)dst, (const float4*)ew,
        nquad, src, dst, ew, ntail, BN);

    // Raw (unnormalized) passes: atomic-free, coalesced bucket walks.
    const float* srcbuf[NUM_PASSES + 1] = { x, pA, pB, pC };
    float*       dstbuf[NUM_PASSES]     = { pA, pB, pC };
    for (int p = 0; p < NUM_PASSES; p++)
        pass_kernel<<<pass_blocks, T>>>(srcbuf[p], dstbuf[p], BN);

    final_kernel<<<NUM_GRAPHS, 256>>>(dm, fc_w, fc_b, out, N, M);
}